// round 3
// baseline (speedup 1.0000x reference)
#include <cuda_runtime.h>

#define NNODES 50000
#define RREL   4
#define EDGES  80000

// Scratch: per-relation GEMM outputs H_r = x @ W_r  (204.8 MB) + degree data.
// NOTE: __device__ symbols are ONLY dereferenced in device code. Host code
// obtains raw pointers exclusively via cudaGetSymbolAddress (passing the
// host-shadow address as a kernel arg silently reads host memory via ATS on
// GB300 — that was the R2 bug).
__device__ float g_H[(size_t)RREL * NNODES * 256];
__device__ int   g_deg[RREL * NNODES];
__device__ float g_invdeg[RREL * NNODES];

// ---------------------------------------------------------------------------
// degree pipeline (tiny)
// ---------------------------------------------------------------------------
__global__ void zero_deg_kernel() {
    int i = blockIdx.x * blockDim.x + threadIdx.x;
    if (i < RREL * NNODES) g_deg[i] = 0;
}

__global__ void deg_kernel(const int* __restrict__ dst) {
    int i = blockIdx.x * blockDim.x + threadIdx.x;
    if (i < RREL * EDGES) {
        int r = i / EDGES;
        atomicAdd(&g_deg[r * NNODES + dst[i]], 1);
    }
}

__global__ void invdeg_kernel() {
    int i = blockIdx.x * blockDim.x + threadIdx.x;
    if (i < RREL * NNODES)
        g_invdeg[i] = 1.0f / fmaxf((float)g_deg[i], 1.0f);
}

// ---------------------------------------------------------------------------
// SGEMM: C[M=50000, 256] = A[50000, 256] @ B[256, 256]
// BM=BN=128, BK=16, 256 threads, 8x8 per thread, double-buffered smem.
// ---------------------------------------------------------------------------
#define BM 128
#define BN 128
#define BK 16

__global__ __launch_bounds__(256, 2)
void gemm_kernel(const float* __restrict__ A,
                 const float* __restrict__ B,
                 float* __restrict__ C) {
    __shared__ float As[2][BK][BM];   // transposed: [k][m]
    __shared__ float Bs[2][BK][BN];   // natural:    [k][n]

    const int tid = threadIdx.x;
    const int m0  = blockIdx.x * BM;
    const int n0  = blockIdx.y * BN;
    const int tx  = tid & 15;
    const int ty  = tid >> 4;

    float acc[8][8];
    #pragma unroll
    for (int i = 0; i < 8; i++)
        #pragma unroll
        for (int j = 0; j < 8; j++) acc[i][j] = 0.f;

    const int NUM_TILES = 256 / BK;   // 16

    float4 aReg[2];
    float4 bReg[2];

    const int aRow0 = tid >> 1;            // 0..127
    const int aKv0  = (tid & 1) * 2;       // float4 index along k: 0 or 2
    const int bRow0 = tid >> 4;            // 0..15
    const int bNv0  = tid & 15;            // float4 index along n

    auto load_tile = [&](int t) {
        int k0 = t << 4;
        int gm = m0 + aRow0;
        if (gm < NNODES) {
            aReg[0] = *reinterpret_cast<const float4*>(A + (size_t)gm * 256 + k0 + aKv0 * 4);
            aReg[1] = *reinterpret_cast<const float4*>(A + (size_t)gm * 256 + k0 + (aKv0 + 1) * 4);
        } else {
            aReg[0] = make_float4(0.f, 0.f, 0.f, 0.f);
            aReg[1] = make_float4(0.f, 0.f, 0.f, 0.f);
        }
        bReg[0] = *reinterpret_cast<const float4*>(B + (size_t)(k0 + bRow0) * 256 + n0 + bNv0 * 4);
        bReg[1] = *reinterpret_cast<const float4*>(B + (size_t)(k0 + bRow0) * 256 + n0 + (bNv0 + 16) * 4);
    };

    auto store_tile = [&](int buf) {
        #pragma unroll
        for (int p = 0; p < 2; p++) {
            int kv = aKv0 + p;
            As[buf][kv * 4 + 0][aRow0] = aReg[p].x;
            As[buf][kv * 4 + 1][aRow0] = aReg[p].y;
            As[buf][kv * 4 + 2][aRow0] = aReg[p].z;
            As[buf][kv * 4 + 3][aRow0] = aReg[p].w;
        }
        *reinterpret_cast<float4*>(&Bs[buf][bRow0][bNv0 * 4])        = bReg[0];
        *reinterpret_cast<float4*>(&Bs[buf][bRow0][(bNv0 + 16) * 4]) = bReg[1];
    };

    load_tile(0);
    store_tile(0);
    __syncthreads();

    int buf = 0;
    for (int t = 0; t < NUM_TILES; t++) {
        if (t + 1 < NUM_TILES) load_tile(t + 1);

        #pragma unroll
        for (int kk = 0; kk < BK; kk++) {
            float a[8], b[8];
            *reinterpret_cast<float4*>(a)     = *reinterpret_cast<const float4*>(&As[buf][kk][ty * 8]);
            *reinterpret_cast<float4*>(a + 4) = *reinterpret_cast<const float4*>(&As[buf][kk][ty * 8 + 4]);
            *reinterpret_cast<float4*>(b)     = *reinterpret_cast<const float4*>(&Bs[buf][kk][tx * 8]);
            *reinterpret_cast<float4*>(b + 4) = *reinterpret_cast<const float4*>(&Bs[buf][kk][tx * 8 + 4]);
            #pragma unroll
            for (int i = 0; i < 8; i++)
                #pragma unroll
                for (int j = 0; j < 8; j++)
                    acc[i][j] += a[i] * b[j];
        }

        if (t + 1 < NUM_TILES) {
            store_tile(buf ^ 1);
            __syncthreads();
            buf ^= 1;
        }
    }

    #pragma unroll
    for (int i = 0; i < 8; i++) {
        int row = m0 + ty * 8 + i;
        if (row < NNODES) {
            #pragma unroll
            for (int j4 = 0; j4 < 2; j4++) {
                float4 o;
                o.x = acc[i][j4 * 4 + 0];
                o.y = acc[i][j4 * 4 + 1];
                o.z = acc[i][j4 * 4 + 2];
                o.w = acc[i][j4 * 4 + 3];
                *reinterpret_cast<float4*>(C + (size_t)row * 256 + n0 + tx * 8 + j4 * 4) = o;
            }
        }
    }
}

// ---------------------------------------------------------------------------
// Scatter for relation r: out[d] += invdeg[r][d] * H_r[s]
// One warp per edge, vec4 global reductions. All device-symbol access stays
// in device code (indexed by the relation id passed by value).
// ---------------------------------------------------------------------------
__global__ void scatter_kernel(const int* __restrict__ src,
                               const int* __restrict__ dst,
                               int r,
                               float* __restrict__ out) {
    int gw   = (blockIdx.x * blockDim.x + threadIdx.x) >> 5;
    int lane = threadIdx.x & 31;
    if (gw >= EDGES) return;
    int s = src[gw];
    int d = dst[gw];
    float w = g_invdeg[r * NNODES + d];

    const float4* h = reinterpret_cast<const float4*>(
        g_H + ((size_t)r * NNODES + s) * 256);
    float* ob = out + (size_t)d * 256;
    #pragma unroll
    for (int i = 0; i < 2; i++) {
        float4 v = __ldg(&h[lane + i * 32]);
        v.x *= w; v.y *= w; v.z *= w; v.w *= w;
        float* a = ob + (size_t)(lane + i * 32) * 4;
        asm volatile("red.global.add.v4.f32 [%0], {%1,%2,%3,%4};"
                     :: "l"(a), "f"(v.x), "f"(v.y), "f"(v.z), "f"(v.w)
                     : "memory");
    }
}

// ---------------------------------------------------------------------------
// Epilogue: out = relu(out + bias), in place (vectorized)
// ---------------------------------------------------------------------------
__global__ void epilogue_kernel(const float* __restrict__ bias,
                                float* __restrict__ out) {
    size_t i = (size_t)blockIdx.x * blockDim.x + threadIdx.x;
    size_t total4 = (size_t)NNODES * 64;
    if (i < total4) {
        float4 v = reinterpret_cast<float4*>(out)[i];
        int c = (int)(i & 63) * 4;
        v.x = fmaxf(v.x + bias[c + 0], 0.f);
        v.y = fmaxf(v.y + bias[c + 1], 0.f);
        v.z = fmaxf(v.z + bias[c + 2], 0.f);
        v.w = fmaxf(v.w + bias[c + 3], 0.f);
        reinterpret_cast<float4*>(out)[i] = v;
    }
}

// ---------------------------------------------------------------------------
extern "C" void kernel_launch(void* const* d_in, const int* in_sizes, int n_in,
                              void* d_out, int out_size) {
    const float* x      = (const float*)d_in[0];   // [N, 256]
    const int*   src    = (const int*)  d_in[1];   // [R, E]
    const int*   dst    = (const int*)  d_in[2];   // [R, E]
    const float* weight = (const float*)d_in[3];   // [R, 256, 256]
    const float* wself  = (const float*)d_in[4];   // [256, 256]
    const float* bias   = (const float*)d_in[5];   // [256]
    float* out = (float*)d_out;                    // [N, 256]

    // Device address of H scratch (the ONLY legal way from host code)
    float* H = nullptr;
    cudaGetSymbolAddress((void**)&H, g_H);

    // degree pipeline
    zero_deg_kernel<<<(RREL * NNODES + 255) / 256, 256>>>();
    deg_kernel<<<(RREL * EDGES + 255) / 256, 256>>>(dst);
    invdeg_kernel<<<(RREL * NNODES + 255) / 256, 256>>>();

    dim3 grid((NNODES + BM - 1) / BM, 256 / BN);   // (391, 2)

    // self-loop GEMM seeds the output accumulator
    gemm_kernel<<<grid, 256>>>(x, wself, out);

    // per relation: H_r = x @ W_r, then scatter-add into out
    int sblocks = (EDGES * 32 + 255) / 256;        // 10000
    for (int r = 0; r < RREL; r++) {
        gemm_kernel<<<grid, 256>>>(x, weight + (size_t)r * 256 * 256,
                                   H + (size_t)r * NNODES * 256);
        scatter_kernel<<<sblocks, 256>>>(src + r * EDGES, dst + r * EDGES,
                                         r, out);
    }

    // bias + relu
    epilogue_kernel<<<(NNODES * 64 + 255) / 256, 256>>>(bias, out);
}

// round 7
// speedup vs baseline: 1.6797x; 1.6797x over previous
#include <cuda_runtime.h>
#include <cuda_bf16.h>
#include <mma.h>
#include <cstdint>

using namespace nvcuda;

#define NNODES 50000
#define NPAD   50048      // padded rows so store_matrix_sync never goes OOB
#define RREL   4
#define EDGES  80000
#define NGEMM  5          // slot 0 = self-loop, 1..4 = relations

// ---------------------------------------------------------------------------
// Static device scratch. Device code references symbols directly (R2 lesson:
// host-shadow addresses silently read host memory via ATS on GB300).
// ---------------------------------------------------------------------------
__device__ float         g_Hp[(size_t)NGEMM * NPAD * 256];    // 256.2 MB
__device__ int           g_deg[RREL * NNODES];
__device__ float         g_invdeg[RREL * NNODES];
__device__ __nv_bfloat16 g_x_hi[(size_t)NNODES * 256];
__device__ __nv_bfloat16 g_x_lo[(size_t)NNODES * 256];
__device__ __nv_bfloat16 g_w_hi[NGEMM * 256 * 256];           // [g][n][k] (W transposed)
__device__ __nv_bfloat16 g_w_lo[NGEMM * 256 * 256];

// ---------------------------------------------------------------------------
// degree pipeline
// ---------------------------------------------------------------------------
__global__ void zero_deg_kernel() {
    int i = blockIdx.x * blockDim.x + threadIdx.x;
    if (i < RREL * NNODES) g_deg[i] = 0;
}
__global__ void deg_kernel(const int* __restrict__ dst) {
    int i = blockIdx.x * blockDim.x + threadIdx.x;
    if (i < RREL * EDGES) {
        int r = i / EDGES;
        atomicAdd(&g_deg[r * NNODES + dst[i]], 1);
    }
}
__global__ void invdeg_kernel() {
    int i = blockIdx.x * blockDim.x + threadIdx.x;
    if (i < RREL * NNODES)
        g_invdeg[i] = 1.0f / fmaxf((float)g_deg[i], 1.0f);
}

// ---------------------------------------------------------------------------
// Prep: split x into bf16 hi/lo (once; shared A operand of all 5 GEMMs)
// ---------------------------------------------------------------------------
__global__ void convert_x_kernel(const float* __restrict__ x) {
    size_t total = (size_t)NNODES * 64;   // float4 count
    for (size_t i = (size_t)blockIdx.x * blockDim.x + threadIdx.x; i < total;
         i += (size_t)gridDim.x * blockDim.x) {
        float4 v = reinterpret_cast<const float4*>(x)[i];
        __nv_bfloat162 h01 = __float22bfloat162_rn(make_float2(v.x, v.y));
        __nv_bfloat162 h23 = __float22bfloat162_rn(make_float2(v.z, v.w));
        float2 f01 = __bfloat1622float2(h01);
        float2 f23 = __bfloat1622float2(h23);
        __nv_bfloat162 l01 = __float22bfloat162_rn(make_float2(v.x - f01.x, v.y - f01.y));
        __nv_bfloat162 l23 = __float22bfloat162_rn(make_float2(v.z - f23.x, v.w - f23.y));
        reinterpret_cast<__nv_bfloat162*>(g_x_hi)[2 * i]     = h01;
        reinterpret_cast<__nv_bfloat162*>(g_x_hi)[2 * i + 1] = h23;
        reinterpret_cast<__nv_bfloat162*>(g_x_lo)[2 * i]     = l01;
        reinterpret_cast<__nv_bfloat162*>(g_x_lo)[2 * i + 1] = l23;
    }
}

// Prep: transpose+split weights into B layout W_t[g][n][k] = W_g[k][n]
__global__ void convert_w_kernel(const float* __restrict__ weight,
                                 const float* __restrict__ wself) {
    int i = blockIdx.x * blockDim.x + threadIdx.x;
    if (i >= NGEMM * 65536) return;
    int g = i >> 16;
    int n = (i >> 8) & 255;
    int k = i & 255;
    const float* src = (g == 0) ? wself : weight + (size_t)(g - 1) * 65536;
    float v = src[k * 256 + n];
    __nv_bfloat16 h = __float2bfloat16_rn(v);
    float r = v - __bfloat162float(h);
    g_w_hi[i] = h;
    g_w_lo[i] = __float2bfloat16_rn(r);
}

// ---------------------------------------------------------------------------
// wmma GEMM: g_Hp[g][0:50048, n0:n0+128] = (x_hi+x_lo) @ (W_hi+W_lo)^T
// 3 terms: hi*hi + hi*lo + lo*hi. grid (391, 2, 5), 256 threads.
// Block tile 128x128, warp tile 32x64 (4 warps in m, 2 in n), K-chunk 32.
// ---------------------------------------------------------------------------
#define KC  32
#define LDS 40    // smem leading dim (bf16 elements), multiple of 8

__global__ void __launch_bounds__(256)
wmma_gemm_kernel() {
    __shared__ __nv_bfloat16 Ah[128][LDS];
    __shared__ __nv_bfloat16 Al[128][LDS];
    __shared__ __nv_bfloat16 Bh[128][LDS];   // [n][k]
    __shared__ __nv_bfloat16 Bl[128][LDS];

    const int tid = threadIdx.x;
    const int wid = tid >> 5;
    const int wm  = wid & 3;          // warp m index: rows wm*32..wm*32+31
    const int wn  = wid >> 2;         // warp n index: cols wn*64..wn*64+63
    const int m0  = blockIdx.x * 128;
    const int n0  = blockIdx.y * 128;
    const int g   = blockIdx.z;

    const __nv_bfloat16* wh = g_w_hi + (size_t)g * 65536;
    const __nv_bfloat16* wl = g_w_lo + (size_t)g * 65536;

    wmma::fragment<wmma::accumulator, 16, 16, 16, float> c[2][4];
    #pragma unroll
    for (int mi = 0; mi < 2; mi++)
        #pragma unroll
        for (int ni = 0; ni < 4; ni++)
            wmma::fill_fragment(c[mi][ni], 0.0f);

    // per-thread tile-load coords: 512 uint4 per tile, 2 per thread
    for (int kc = 0; kc < 8; kc++) {
        const int k0 = kc * KC;

        #pragma unroll
        for (int t = 0; t < 2; t++) {
            int idx = tid + t * 256;          // 0..511
            int row = idx >> 2;               // 0..127
            int c4  = idx & 3;                // uint4 within the 32-k row
            int kof = k0 + c4 * 8;            // 8 bf16 per uint4

            // A rows need a bounds guard (x is exactly 50000 rows)
            int gm = m0 + row;
            uint4 vh, vl;
            if (gm < NNODES) {
                vh = *reinterpret_cast<const uint4*>(g_x_hi + (size_t)gm * 256 + kof);
                vl = *reinterpret_cast<const uint4*>(g_x_lo + (size_t)gm * 256 + kof);
            } else {
                vh = make_uint4(0u, 0u, 0u, 0u); vl = vh;
            }
            *reinterpret_cast<uint4*>(&Ah[row][c4 * 8]) = vh;
            *reinterpret_cast<uint4*>(&Al[row][c4 * 8]) = vl;

            // B rows n0+row < 256 always
            int n = n0 + row;
            *reinterpret_cast<uint4*>(&Bh[row][c4 * 8]) =
                *reinterpret_cast<const uint4*>(wh + (size_t)n * 256 + kof);
            *reinterpret_cast<uint4*>(&Bl[row][c4 * 8]) =
                *reinterpret_cast<const uint4*>(wl + (size_t)n * 256 + kof);
        }
        __syncthreads();

        #pragma unroll
        for (int ks = 0; ks < 2; ks++) {
            const int kk = ks * 16;
            wmma::fragment<wmma::matrix_a, 16, 16, 16, __nv_bfloat16, wmma::row_major> ah[2], al[2];
            wmma::fragment<wmma::matrix_b, 16, 16, 16, __nv_bfloat16, wmma::col_major> bh[4], bl[4];
            #pragma unroll
            for (int mi = 0; mi < 2; mi++) {
                wmma::load_matrix_sync(ah[mi], &Ah[wm * 32 + mi * 16][kk], LDS);
                wmma::load_matrix_sync(al[mi], &Al[wm * 32 + mi * 16][kk], LDS);
            }
            #pragma unroll
            for (int ni = 0; ni < 4; ni++) {
                wmma::load_matrix_sync(bh[ni], &Bh[wn * 64 + ni * 16][kk], LDS);
                wmma::load_matrix_sync(bl[ni], &Bl[wn * 64 + ni * 16][kk], LDS);
            }
            #pragma unroll
            for (int mi = 0; mi < 2; mi++)
                #pragma unroll
                for (int ni = 0; ni < 4; ni++) {
                    wmma::mma_sync(c[mi][ni], ah[mi], bh[ni], c[mi][ni]);
                    wmma::mma_sync(c[mi][ni], ah[mi], bl[ni], c[mi][ni]);
                    wmma::mma_sync(c[mi][ni], al[mi], bh[ni], c[mi][ni]);
                }
        }
        __syncthreads();
    }

    // store into padded H (rows < 50048 always in-bounds; no predication)
    float* Cg = g_Hp + (size_t)g * NPAD * 256;
    #pragma unroll
    for (int mi = 0; mi < 2; mi++)
        #pragma unroll
        for (int ni = 0; ni < 4; ni++) {
            int row = m0 + wm * 32 + mi * 16;
            int col = n0 + wn * 64 + ni * 16;
            wmma::store_matrix_sync(Cg + (size_t)row * 256 + col, c[mi][ni],
                                    256, wmma::mem_row_major);
        }
}

// ---------------------------------------------------------------------------
// Seed out with the self-loop term: out = Hp[0][0:50000]
// ---------------------------------------------------------------------------
__global__ void copy_out_kernel(float* __restrict__ out) {
    size_t total = (size_t)NNODES * 64;
    for (size_t i = (size_t)blockIdx.x * blockDim.x + threadIdx.x; i < total;
         i += (size_t)gridDim.x * blockDim.x) {
        reinterpret_cast<float4*>(out)[i] =
            reinterpret_cast<const float4*>(g_Hp)[i];
    }
}

// ---------------------------------------------------------------------------
// Scatter relation r: out[d] += invdeg[r][d] * Hp[r+1][s]  (one warp per edge)
// ---------------------------------------------------------------------------
__global__ void scatter_kernel(const int* __restrict__ src,
                               const int* __restrict__ dst,
                               int r, float* __restrict__ out) {
    int gw   = (blockIdx.x * blockDim.x + threadIdx.x) >> 5;
    int lane = threadIdx.x & 31;
    if (gw >= EDGES) return;
    int s = src[gw];
    int d = dst[gw];
    float w = g_invdeg[r * NNODES + d];

    const float4* h = reinterpret_cast<const float4*>(
        g_Hp + ((size_t)(r + 1) * NPAD + s) * 256);
    float* ob = out + (size_t)d * 256;
    #pragma unroll
    for (int i = 0; i < 2; i++) {
        float4 v = __ldg(&h[lane + i * 32]);
        v.x *= w; v.y *= w; v.z *= w; v.w *= w;
        float* a = ob + (size_t)(lane + i * 32) * 4;
        asm volatile("red.global.add.v4.f32 [%0], {%1,%2,%3,%4};"
                     :: "l"(a), "f"(v.x), "f"(v.y), "f"(v.z), "f"(v.w) : "memory");
    }
}

// ---------------------------------------------------------------------------
// Epilogue: out = relu(out + bias), in place
// ---------------------------------------------------------------------------
__global__ void epilogue_kernel(const float* __restrict__ bias,
                                float* __restrict__ out) {
    size_t i = (size_t)blockIdx.x * blockDim.x + threadIdx.x;
    size_t total4 = (size_t)NNODES * 64;
    if (i < total4) {
        float4 v = reinterpret_cast<float4*>(out)[i];
        int c = (int)(i & 63) * 4;
        v.x = fmaxf(v.x + bias[c + 0], 0.f);
        v.y = fmaxf(v.y + bias[c + 1], 0.f);
        v.z = fmaxf(v.z + bias[c + 2], 0.f);
        v.w = fmaxf(v.w + bias[c + 3], 0.f);
        reinterpret_cast<float4*>(out)[i] = v;
    }
}

// ---------------------------------------------------------------------------
extern "C" void kernel_launch(void* const* d_in, const int* in_sizes, int n_in,
                              void* d_out, int out_size) {
    const float* x      = (const float*)d_in[0];
    const int*   src    = (const int*)  d_in[1];
    const int*   dst    = (const int*)  d_in[2];
    const float* weight = (const float*)d_in[3];
    const float* wself  = (const float*)d_in[4];
    const float* bias   = (const float*)d_in[5];
    float* out = (float*)d_out;

    // degree pipeline + operand conversion
    zero_deg_kernel<<<(RREL * NNODES + 255) / 256, 256>>>();
    deg_kernel<<<(RREL * EDGES + 255) / 256, 256>>>(dst);
    invdeg_kernel<<<(RREL * NNODES + 255) / 256, 256>>>();
    convert_x_kernel<<<2048, 256>>>(x);
    convert_w_kernel<<<(NGEMM * 65536 + 255) / 256, 256>>>(weight, wself);

    // all 5 GEMMs in one launch (writes padded H)
    wmma_gemm_kernel<<<dim3(391, 2, NGEMM), 256>>>();

    // out = self-loop term, then scatter the 4 relations into it
    copy_out_kernel<<<2048, 256>>>(out);
    int sblocks = (EDGES * 32 + 255) / 256;
    for (int r = 0; r < RREL; r++)
        scatter_kernel<<<sblocks, 256>>>(src + r * EDGES, dst + r * EDGES, r, out);

    epilogue_kernel<<<(NNODES * 64 + 255) / 256, 256>>>(bias, out);
}

// round 8
// speedup vs baseline: 1.9282x; 1.1479x over previous
#include <cuda_runtime.h>
#include <cuda_bf16.h>
#include <mma.h>
#include <cstdint>

using namespace nvcuda;

#define NNODES 50000
#define NPAD   50048      // padded rows so store_matrix_sync never goes OOB
#define RREL   4
#define EDGES  80000
#define NGEMM  5          // slot 0 = self-loop, 1..4 = relations

// ---------------------------------------------------------------------------
// Static device scratch. Device code references symbols directly (R2 lesson:
// host-shadow addresses silently read host memory via ATS on GB300).
// ---------------------------------------------------------------------------
__device__ float         g_Hp[(size_t)NGEMM * NPAD * 256];    // 256.2 MB
__device__ int           g_deg[RREL * NNODES];
__device__ float         g_invdeg[RREL * NNODES];
__device__ __nv_bfloat16 g_x_hi[(size_t)NNODES * 256];
__device__ __nv_bfloat16 g_x_lo[(size_t)NNODES * 256];
__device__ __nv_bfloat16 g_w_hi[NGEMM * 256 * 256];           // [g][n][k] (W transposed)
__device__ __nv_bfloat16 g_w_lo[NGEMM * 256 * 256];

// ---------------------------------------------------------------------------
// degree pipeline
// ---------------------------------------------------------------------------
__global__ void zero_deg_kernel() {
    int i = blockIdx.x * blockDim.x + threadIdx.x;
    if (i < RREL * NNODES) g_deg[i] = 0;
}
__global__ void deg_kernel(const int* __restrict__ dst) {
    int i = blockIdx.x * blockDim.x + threadIdx.x;
    if (i < RREL * EDGES) {
        int r = i / EDGES;
        atomicAdd(&g_deg[r * NNODES + dst[i]], 1);
    }
}
__global__ void invdeg_kernel() {
    int i = blockIdx.x * blockDim.x + threadIdx.x;
    if (i < RREL * NNODES)
        g_invdeg[i] = 1.0f / fmaxf((float)g_deg[i], 1.0f);
}

// ---------------------------------------------------------------------------
// Prep: split x into bf16 hi/lo (once; shared A operand of all 5 GEMMs)
// ---------------------------------------------------------------------------
__global__ void convert_x_kernel(const float* __restrict__ x) {
    size_t total = (size_t)NNODES * 64;   // float4 count
    for (size_t i = (size_t)blockIdx.x * blockDim.x + threadIdx.x; i < total;
         i += (size_t)gridDim.x * blockDim.x) {
        float4 v = reinterpret_cast<const float4*>(x)[i];
        __nv_bfloat162 h01 = __float22bfloat162_rn(make_float2(v.x, v.y));
        __nv_bfloat162 h23 = __float22bfloat162_rn(make_float2(v.z, v.w));
        float2 f01 = __bfloat1622float2(h01);
        float2 f23 = __bfloat1622float2(h23);
        __nv_bfloat162 l01 = __float22bfloat162_rn(make_float2(v.x - f01.x, v.y - f01.y));
        __nv_bfloat162 l23 = __float22bfloat162_rn(make_float2(v.z - f23.x, v.w - f23.y));
        reinterpret_cast<__nv_bfloat162*>(g_x_hi)[2 * i]     = h01;
        reinterpret_cast<__nv_bfloat162*>(g_x_hi)[2 * i + 1] = h23;
        reinterpret_cast<__nv_bfloat162*>(g_x_lo)[2 * i]     = l01;
        reinterpret_cast<__nv_bfloat162*>(g_x_lo)[2 * i + 1] = l23;
    }
}

// Prep: transpose+split weights into B layout W_t[g][n][k] = W_g[k][n]
__global__ void convert_w_kernel(const float* __restrict__ weight,
                                 const float* __restrict__ wself) {
    int i = blockIdx.x * blockDim.x + threadIdx.x;
    if (i >= NGEMM * 65536) return;
    int g = i >> 16;
    int n = (i >> 8) & 255;
    int k = i & 255;
    const float* src = (g == 0) ? wself : weight + (size_t)(g - 1) * 65536;
    float v = src[k * 256 + n];
    __nv_bfloat16 h = __float2bfloat16_rn(v);
    float r = v - __bfloat162float(h);
    g_w_hi[i] = h;
    g_w_lo[i] = __float2bfloat16_rn(r);
}

// ---------------------------------------------------------------------------
// wmma GEMM with cp.async double buffering.
// g_Hp[g][:, n0:n0+128] = (x_hi+x_lo) @ (W_hi+W_lo)^T  (3 terms)
// grid (391, 2, 5), 256 threads. Block tile 128x128, warp tile 32x64, KC=32.
// Dynamic smem: 2 stages x 4 matrices x [128][LDS] bf16 = 81920 B.
// ---------------------------------------------------------------------------
#define KC   32
#define LDS  40                   // row stride (bf16); 80 B, 16B-aligned
#define TILE_ELEMS (128 * LDS)    // 5120

__device__ __forceinline__ uint32_t smem_u32(const void* p) {
    uint32_t a;
    asm("{ .reg .u64 t; cvta.to.shared.u64 t, %1; cvt.u32.u64 %0, t; }" : "=r"(a) : "l"(p));
    return a;
}
__device__ __forceinline__ void cpa16(uint32_t dst, const void* src) {
    asm volatile("cp.async.cg.shared.global [%0], [%1], 16;" :: "r"(dst), "l"(src));
}
__device__ __forceinline__ void cpa16_zfill(uint32_t dst, const void* src) {
    asm volatile("cp.async.cg.shared.global [%0], [%1], 16, 0;" :: "r"(dst), "l"(src));
}

__global__ void __launch_bounds__(256)
wmma_gemm_kernel() {
    extern __shared__ __nv_bfloat16 smem[];

    const int tid = threadIdx.x;
    const int wid = tid >> 5;
    const int wm  = wid & 3;          // warp rows wm*32..+31
    const int wn  = wid >> 2;         // warp cols wn*64..+63
    const int m0  = blockIdx.x * 128;
    const int n0  = blockIdx.y * 128;
    const int g   = blockIdx.z;

    const __nv_bfloat16* wh = g_w_hi + (size_t)g * 65536;
    const __nv_bfloat16* wl = g_w_lo + (size_t)g * 65536;

    // per-thread load coords (512 uint4 per matrix tile, 2 per thread)
    const int lrow0 = tid >> 2;                 // 0..63
    const int lc4   = tid & 3;                  // uint4 slot in 32-wide k row
    // thread handles rows lrow0 and lrow0+64 for each matrix

    auto issue_tile = [&](int t) {
        const int k0 = t * KC;
        const int stage = t & 1;
        __nv_bfloat16* Ah = smem + (stage * 4 + 0) * TILE_ELEMS;
        __nv_bfloat16* Al = smem + (stage * 4 + 1) * TILE_ELEMS;
        __nv_bfloat16* Bh = smem + (stage * 4 + 2) * TILE_ELEMS;
        __nv_bfloat16* Bl = smem + (stage * 4 + 3) * TILE_ELEMS;
        #pragma unroll
        for (int p = 0; p < 2; p++) {
            int row = lrow0 + p * 64;
            int kof = k0 + lc4 * 8;
            uint32_t soff = (uint32_t)(row * LDS + lc4 * 8) * 2;  // bytes
            int gm = m0 + row;
            const void* a_h = g_x_hi + (size_t)gm * 256 + kof;
            const void* a_l = g_x_lo + (size_t)gm * 256 + kof;
            if (gm < NNODES) {
                cpa16(smem_u32(Ah) + soff, a_h);
                cpa16(smem_u32(Al) + soff, a_l);
            } else {
                cpa16_zfill(smem_u32(Ah) + soff, g_x_hi);
                cpa16_zfill(smem_u32(Al) + soff, g_x_lo);
            }
            int n = n0 + row;
            cpa16(smem_u32(Bh) + soff, wh + (size_t)n * 256 + kof);
            cpa16(smem_u32(Bl) + soff, wl + (size_t)n * 256 + kof);
        }
        asm volatile("cp.async.commit_group;" ::: "memory");
    };

    wmma::fragment<wmma::accumulator, 16, 16, 16, float> c[2][4];
    #pragma unroll
    for (int mi = 0; mi < 2; mi++)
        #pragma unroll
        for (int ni = 0; ni < 4; ni++)
            wmma::fill_fragment(c[mi][ni], 0.0f);

    issue_tile(0);

    for (int t = 0; t < 8; t++) {
        if (t + 1 < 8) {
            issue_tile(t + 1);
            asm volatile("cp.async.wait_group 1;" ::: "memory");
        } else {
            asm volatile("cp.async.wait_group 0;" ::: "memory");
        }
        __syncthreads();   // stage t data visible to all warps

        const int stage = t & 1;
        const __nv_bfloat16* Ah = smem + (stage * 4 + 0) * TILE_ELEMS;
        const __nv_bfloat16* Al = smem + (stage * 4 + 1) * TILE_ELEMS;
        const __nv_bfloat16* Bh = smem + (stage * 4 + 2) * TILE_ELEMS;
        const __nv_bfloat16* Bl = smem + (stage * 4 + 3) * TILE_ELEMS;

        #pragma unroll
        for (int ks = 0; ks < 2; ks++) {
            const int kk = ks * 16;
            wmma::fragment<wmma::matrix_a, 16, 16, 16, __nv_bfloat16, wmma::row_major> ah[2], al[2];
            wmma::fragment<wmma::matrix_b, 16, 16, 16, __nv_bfloat16, wmma::col_major> bh[4], bl[4];
            #pragma unroll
            for (int mi = 0; mi < 2; mi++) {
                wmma::load_matrix_sync(ah[mi], Ah + (wm * 32 + mi * 16) * LDS + kk, LDS);
                wmma::load_matrix_sync(al[mi], Al + (wm * 32 + mi * 16) * LDS + kk, LDS);
            }
            #pragma unroll
            for (int ni = 0; ni < 4; ni++) {
                wmma::load_matrix_sync(bh[ni], Bh + (wn * 64 + ni * 16) * LDS + kk, LDS);
                wmma::load_matrix_sync(bl[ni], Bl + (wn * 64 + ni * 16) * LDS + kk, LDS);
            }
            #pragma unroll
            for (int mi = 0; mi < 2; mi++)
                #pragma unroll
                for (int ni = 0; ni < 4; ni++) {
                    wmma::mma_sync(c[mi][ni], ah[mi], bh[ni], c[mi][ni]);
                    wmma::mma_sync(c[mi][ni], ah[mi], bl[ni], c[mi][ni]);
                    wmma::mma_sync(c[mi][ni], al[mi], bh[ni], c[mi][ni]);
                }
        }
        __syncthreads();   // all warps done with stage t before it is reloaded
    }

    // store into padded H (rows < 50048 always in-bounds)
    float* Cg = g_Hp + (size_t)g * NPAD * 256;
    #pragma unroll
    for (int mi = 0; mi < 2; mi++)
        #pragma unroll
        for (int ni = 0; ni < 4; ni++) {
            int row = m0 + wm * 32 + mi * 16;
            int col = n0 + wn * 64 + ni * 16;
            wmma::store_matrix_sync(Cg + (size_t)row * 256 + col, c[mi][ni],
                                    256, wmma::mem_row_major);
        }
}

// ---------------------------------------------------------------------------
// Scatter ALL relations in one launch: Hp[0][d] += invdeg[r][d] * Hp[r+1][s]
// (one warp per edge; Hp[0] already holds the self-loop term)
// ---------------------------------------------------------------------------
__global__ void scatter_all_kernel(const int* __restrict__ src,
                                   const int* __restrict__ dst) {
    int gw   = (blockIdx.x * blockDim.x + threadIdx.x) >> 5;
    int lane = threadIdx.x & 31;
    if (gw >= RREL * EDGES) return;
    int r = gw / EDGES;
    int s = src[gw];
    int d = dst[gw];
    float w = g_invdeg[r * NNODES + d];

    const float4* h = reinterpret_cast<const float4*>(
        g_Hp + ((size_t)(r + 1) * NPAD + s) * 256);
    float* ob = g_Hp + (size_t)d * 256;     // accumulate into Hp[0]
    #pragma unroll
    for (int i = 0; i < 2; i++) {
        float4 v = __ldg(&h[lane + i * 32]);
        v.x *= w; v.y *= w; v.z *= w; v.w *= w;
        float* a = ob + (size_t)(lane + i * 32) * 4;
        asm volatile("red.global.add.v4.f32 [%0], {%1,%2,%3,%4};"
                     :: "l"(a), "f"(v.x), "f"(v.y), "f"(v.z), "f"(v.w) : "memory");
    }
}

// ---------------------------------------------------------------------------
// Epilogue: out = relu(Hp[0] + bias)
// ---------------------------------------------------------------------------
__global__ void epilogue_kernel(const float* __restrict__ bias,
                                float* __restrict__ out) {
    size_t i = (size_t)blockIdx.x * blockDim.x + threadIdx.x;
    size_t total4 = (size_t)NNODES * 64;
    if (i < total4) {
        float4 v = reinterpret_cast<const float4*>(g_Hp)[i];
        int c = (int)(i & 63) * 4;
        v.x = fmaxf(v.x + bias[c + 0], 0.f);
        v.y = fmaxf(v.y + bias[c + 1], 0.f);
        v.z = fmaxf(v.z + bias[c + 2], 0.f);
        v.w = fmaxf(v.w + bias[c + 3], 0.f);
        reinterpret_cast<float4*>(out)[i] = v;
    }
}

// ---------------------------------------------------------------------------
extern "C" void kernel_launch(void* const* d_in, const int* in_sizes, int n_in,
                              void* d_out, int out_size) {
    const float* x      = (const float*)d_in[0];
    const int*   src    = (const int*)  d_in[1];
    const int*   dst    = (const int*)  d_in[2];
    const float* weight = (const float*)d_in[3];
    const float* wself  = (const float*)d_in[4];
    const float* bias   = (const float*)d_in[5];
    float* out = (float*)d_out;

    const int SMEM_BYTES = 2 * 4 * TILE_ELEMS * 2;   // 81920
    cudaFuncSetAttribute(wmma_gemm_kernel,
                         cudaFuncAttributeMaxDynamicSharedMemorySize, SMEM_BYTES);

    // degree pipeline + operand conversion
    zero_deg_kernel<<<(RREL * NNODES + 255) / 256, 256>>>();
    deg_kernel<<<(RREL * EDGES + 255) / 256, 256>>>(dst);
    invdeg_kernel<<<(RREL * NNODES + 255) / 256, 256>>>();
    convert_x_kernel<<<2048, 256>>>(x);
    convert_w_kernel<<<(NGEMM * 65536 + 255) / 256, 256>>>(weight, wself);

    // all 5 GEMMs in one launch (writes padded Hp; slot 0 = self-loop)
    wmma_gemm_kernel<<<dim3(391, 2, NGEMM), 256, SMEM_BYTES>>>();

    // one merged scatter launch: accumulate all relations into Hp[0]
    int sblocks = (RREL * EDGES * 32 + 255) / 256;   // 40000
    scatter_all_kernel<<<sblocks, 256>>>(src, dst);

    // out = relu(Hp[0] + bias)
    epilogue_kernel<<<(NNODES * 64 + 255) / 256, 256>>>(bias, out);
}

// round 9
// speedup vs baseline: 2.4284x; 1.2594x over previous
#include <cuda_runtime.h>
#include <cuda_bf16.h>
#include <mma.h>
#include <cstdint>

using namespace nvcuda;

#define NNODES 50000
#define NPAD   50048      // padded rows so store_matrix_sync never goes OOB
#define RREL   4
#define EDGES  80000
#define NGEMM  5          // slot 0 = self-loop, 1..4 = relations

// ---------------------------------------------------------------------------
// Static device scratch. Device code references symbols directly (R2 lesson:
// host-shadow addresses silently read host memory via ATS on GB300).
// ---------------------------------------------------------------------------
__device__ float         g_Hp[(size_t)NGEMM * NPAD * 256];    // 256.2 MB
__device__ int           g_deg[RREL * NNODES];
__device__ float         g_invdeg[RREL * NNODES];
__device__ __nv_bfloat16 g_x_hi[(size_t)NNODES * 256];
__device__ __nv_bfloat16 g_x_lo[(size_t)NNODES * 256];
__device__ __nv_bfloat16 g_w_hi[NGEMM * 256 * 256];           // [g][n][k] (W transposed)
__device__ __nv_bfloat16 g_w_lo[NGEMM * 256 * 256];

// ---------------------------------------------------------------------------
// degree pipeline
// ---------------------------------------------------------------------------
__global__ void zero_deg_kernel() {
    int i = blockIdx.x * blockDim.x + threadIdx.x;
    if (i < RREL * NNODES) g_deg[i] = 0;
}
__global__ void deg_kernel(const int* __restrict__ dst) {
    int i = blockIdx.x * blockDim.x + threadIdx.x;
    if (i < RREL * EDGES) {
        int r = i / EDGES;
        atomicAdd(&g_deg[r * NNODES + dst[i]], 1);
    }
}
__global__ void invdeg_kernel() {
    int i = blockIdx.x * blockDim.x + threadIdx.x;
    if (i < RREL * NNODES)
        g_invdeg[i] = 1.0f / fmaxf((float)g_deg[i], 1.0f);
}

// ---------------------------------------------------------------------------
// Prep: split x into bf16 hi/lo (once; shared A operand of all 5 GEMMs)
// ---------------------------------------------------------------------------
__global__ void convert_x_kernel(const float* __restrict__ x) {
    size_t total = (size_t)NNODES * 64;   // float4 count
    for (size_t i = (size_t)blockIdx.x * blockDim.x + threadIdx.x; i < total;
         i += (size_t)gridDim.x * blockDim.x) {
        float4 v = reinterpret_cast<const float4*>(x)[i];
        __nv_bfloat162 h01 = __float22bfloat162_rn(make_float2(v.x, v.y));
        __nv_bfloat162 h23 = __float22bfloat162_rn(make_float2(v.z, v.w));
        float2 f01 = __bfloat1622float2(h01);
        float2 f23 = __bfloat1622float2(h23);
        __nv_bfloat162 l01 = __float22bfloat162_rn(make_float2(v.x - f01.x, v.y - f01.y));
        __nv_bfloat162 l23 = __float22bfloat162_rn(make_float2(v.z - f23.x, v.w - f23.y));
        reinterpret_cast<__nv_bfloat162*>(g_x_hi)[2 * i]     = h01;
        reinterpret_cast<__nv_bfloat162*>(g_x_hi)[2 * i + 1] = h23;
        reinterpret_cast<__nv_bfloat162*>(g_x_lo)[2 * i]     = l01;
        reinterpret_cast<__nv_bfloat162*>(g_x_lo)[2 * i + 1] = l23;
    }
}

// Prep: transpose+split weights into B layout W_t[g][n][k] = W_g[k][n]
__global__ void convert_w_kernel(const float* __restrict__ weight,
                                 const float* __restrict__ wself) {
    int i = blockIdx.x * blockDim.x + threadIdx.x;
    if (i >= NGEMM * 65536) return;
    int g = i >> 16;
    int n = (i >> 8) & 255;
    int k = i & 255;
    const float* src = (g == 0) ? wself : weight + (size_t)(g - 1) * 65536;
    float v = src[k * 256 + n];
    __nv_bfloat16 h = __float2bfloat16_rn(v);
    float r = v - __bfloat162float(h);
    g_w_hi[i] = h;
    g_w_lo[i] = __float2bfloat16_rn(r);
}

// ---------------------------------------------------------------------------
// wmma GEMM, cp.async double-buffered, warp tile 64x64.
// g_Hp[g][:, n0:n0+128] = (x_hi+x_lo) @ (W_hi+W_lo)^T  (3 terms)
// grid (391, 2, 5), 128 threads (4 warps, 2x2). Block tile 128x128, KC=32.
// Dynamic smem: 2 stages x 4 matrices x [128][LDS] bf16 = 81920 B.
// ---------------------------------------------------------------------------
#define KC   32
#define LDS  40                   // row stride (bf16); 80 B, 16B-aligned
#define TILE_ELEMS (128 * LDS)    // 5120

__device__ __forceinline__ uint32_t smem_u32(const void* p) {
    uint32_t a;
    asm("{ .reg .u64 t; cvta.to.shared.u64 t, %1; cvt.u32.u64 %0, t; }" : "=r"(a) : "l"(p));
    return a;
}
__device__ __forceinline__ void cpa16(uint32_t dst, const void* src) {
    asm volatile("cp.async.cg.shared.global [%0], [%1], 16;" :: "r"(dst), "l"(src));
}
__device__ __forceinline__ void cpa16_zfill(uint32_t dst, const void* src) {
    asm volatile("cp.async.cg.shared.global [%0], [%1], 16, 0;" :: "r"(dst), "l"(src));
}

__global__ void __launch_bounds__(128)
wmma_gemm_kernel() {
    extern __shared__ __nv_bfloat16 smem[];

    const int tid = threadIdx.x;
    const int wid = tid >> 5;
    const int wm  = wid & 1;          // warp rows wm*64..+63
    const int wn  = wid >> 1;         // warp cols wn*64..+63
    const int m0  = blockIdx.x * 128;
    const int n0  = blockIdx.y * 128;
    const int g   = blockIdx.z;

    const __nv_bfloat16* wh = g_w_hi + (size_t)g * 65536;
    const __nv_bfloat16* wl = g_w_lo + (size_t)g * 65536;

    // per-thread load coords: 512 uint4 per matrix tile, 4 per thread
    const int lrow0 = tid >> 2;                 // 0..31
    const int lc4   = tid & 3;                  // uint4 slot in 32-wide k row

    auto issue_tile = [&](int t) {
        const int k0 = t * KC;
        const int stage = t & 1;
        __nv_bfloat16* Ah = smem + (stage * 4 + 0) * TILE_ELEMS;
        __nv_bfloat16* Al = smem + (stage * 4 + 1) * TILE_ELEMS;
        __nv_bfloat16* Bh = smem + (stage * 4 + 2) * TILE_ELEMS;
        __nv_bfloat16* Bl = smem + (stage * 4 + 3) * TILE_ELEMS;
        #pragma unroll
        for (int p = 0; p < 4; p++) {
            int row = lrow0 + p * 32;
            int kof = k0 + lc4 * 8;
            uint32_t soff = (uint32_t)(row * LDS + lc4 * 8) * 2;  // bytes
            int gm = m0 + row;
            if (gm < NNODES) {
                cpa16(smem_u32(Ah) + soff, g_x_hi + (size_t)gm * 256 + kof);
                cpa16(smem_u32(Al) + soff, g_x_lo + (size_t)gm * 256 + kof);
            } else {
                cpa16_zfill(smem_u32(Ah) + soff, g_x_hi);
                cpa16_zfill(smem_u32(Al) + soff, g_x_lo);
            }
            int n = n0 + row;
            cpa16(smem_u32(Bh) + soff, wh + (size_t)n * 256 + kof);
            cpa16(smem_u32(Bl) + soff, wl + (size_t)n * 256 + kof);
        }
        asm volatile("cp.async.commit_group;" ::: "memory");
    };

    wmma::fragment<wmma::accumulator, 16, 16, 16, float> c[4][4];
    #pragma unroll
    for (int mi = 0; mi < 4; mi++)
        #pragma unroll
        for (int ni = 0; ni < 4; ni++)
            wmma::fill_fragment(c[mi][ni], 0.0f);

    issue_tile(0);

    for (int t = 0; t < 8; t++) {
        if (t + 1 < 8) {
            issue_tile(t + 1);
            asm volatile("cp.async.wait_group 1;" ::: "memory");
        } else {
            asm volatile("cp.async.wait_group 0;" ::: "memory");
        }
        __syncthreads();   // stage t data visible to all warps

        const int stage = t & 1;
        const __nv_bfloat16* Ah = smem + (stage * 4 + 0) * TILE_ELEMS;
        const __nv_bfloat16* Al = smem + (stage * 4 + 1) * TILE_ELEMS;
        const __nv_bfloat16* Bh = smem + (stage * 4 + 2) * TILE_ELEMS;
        const __nv_bfloat16* Bl = smem + (stage * 4 + 3) * TILE_ELEMS;

        #pragma unroll
        for (int ks = 0; ks < 2; ks++) {
            const int kk = ks * 16;
            wmma::fragment<wmma::matrix_a, 16, 16, 16, __nv_bfloat16, wmma::row_major> ah[4], al[4];
            wmma::fragment<wmma::matrix_b, 16, 16, 16, __nv_bfloat16, wmma::col_major> bh[4], bl[4];
            #pragma unroll
            for (int mi = 0; mi < 4; mi++) {
                wmma::load_matrix_sync(ah[mi], Ah + (wm * 64 + mi * 16) * LDS + kk, LDS);
                wmma::load_matrix_sync(al[mi], Al + (wm * 64 + mi * 16) * LDS + kk, LDS);
            }
            #pragma unroll
            for (int ni = 0; ni < 4; ni++) {
                wmma::load_matrix_sync(bh[ni], Bh + (wn * 64 + ni * 16) * LDS + kk, LDS);
                wmma::load_matrix_sync(bl[ni], Bl + (wn * 64 + ni * 16) * LDS + kk, LDS);
            }
            #pragma unroll
            for (int mi = 0; mi < 4; mi++)
                #pragma unroll
                for (int ni = 0; ni < 4; ni++) {
                    wmma::mma_sync(c[mi][ni], ah[mi], bh[ni], c[mi][ni]);
                    wmma::mma_sync(c[mi][ni], ah[mi], bl[ni], c[mi][ni]);
                    wmma::mma_sync(c[mi][ni], al[mi], bh[ni], c[mi][ni]);
                }
        }
        __syncthreads();   // all warps done with stage t before it is reloaded
    }

    // store into padded H (rows < 50048 always in-bounds)
    float* Cg = g_Hp + (size_t)g * NPAD * 256;
    #pragma unroll
    for (int mi = 0; mi < 4; mi++)
        #pragma unroll
        for (int ni = 0; ni < 4; ni++) {
            int row = m0 + wm * 64 + mi * 16;
            int col = n0 + wn * 64 + ni * 16;
            wmma::store_matrix_sync(Cg + (size_t)row * 256 + col, c[mi][ni],
                                    256, wmma::mem_row_major);
        }
}

// ---------------------------------------------------------------------------
// Scatter ALL relations in one launch: Hp[0][d] += invdeg[r][d] * Hp[r+1][s]
// (one warp per edge; Hp[0] already holds the self-loop term)
// ---------------------------------------------------------------------------
__global__ void scatter_all_kernel(const int* __restrict__ src,
                                   const int* __restrict__ dst) {
    int gw   = (blockIdx.x * blockDim.x + threadIdx.x) >> 5;
    int lane = threadIdx.x & 31;
    if (gw >= RREL * EDGES) return;
    int r = gw / EDGES;
    int s = src[gw];
    int d = dst[gw];
    float w = g_invdeg[r * NNODES + d];

    const float4* h = reinterpret_cast<const float4*>(
        g_Hp + ((size_t)(r + 1) * NPAD + s) * 256);
    float* ob = g_Hp + (size_t)d * 256;     // accumulate into Hp[0]
    #pragma unroll
    for (int i = 0; i < 2; i++) {
        float4 v = __ldg(&h[lane + i * 32]);
        v.x *= w; v.y *= w; v.z *= w; v.w *= w;
        float* a = ob + (size_t)(lane + i * 32) * 4;
        asm volatile("red.global.add.v4.f32 [%0], {%1,%2,%3,%4};"
                     :: "l"(a), "f"(v.x), "f"(v.y), "f"(v.z), "f"(v.w) : "memory");
    }
}

// ---------------------------------------------------------------------------
// Epilogue: out = relu(Hp[0] + bias)
// ---------------------------------------------------------------------------
__global__ void epilogue_kernel(const float* __restrict__ bias,
                                float* __restrict__ out) {
    size_t i = (size_t)blockIdx.x * blockDim.x + threadIdx.x;
    size_t total4 = (size_t)NNODES * 64;
    if (i < total4) {
        float4 v = reinterpret_cast<const float4*>(g_Hp)[i];
        int c = (int)(i & 63) * 4;
        v.x = fmaxf(v.x + bias[c + 0], 0.f);
        v.y = fmaxf(v.y + bias[c + 1], 0.f);
        v.z = fmaxf(v.z + bias[c + 2], 0.f);
        v.w = fmaxf(v.w + bias[c + 3], 0.f);
        reinterpret_cast<float4*>(out)[i] = v;
    }
}

// ---------------------------------------------------------------------------
extern "C" void kernel_launch(void* const* d_in, const int* in_sizes, int n_in,
                              void* d_out, int out_size) {
    const float* x      = (const float*)d_in[0];
    const int*   src    = (const int*)  d_in[1];
    const int*   dst    = (const int*)  d_in[2];
    const float* weight = (const float*)d_in[3];
    const float* wself  = (const float*)d_in[4];
    const float* bias   = (const float*)d_in[5];
    float* out = (float*)d_out;

    const int SMEM_BYTES = 2 * 4 * TILE_ELEMS * 2;   // 81920
    cudaFuncSetAttribute(wmma_gemm_kernel,
                         cudaFuncAttributeMaxDynamicSharedMemorySize, SMEM_BYTES);

    // Launch order puts wmma_gemm at captured-profile index 3.
    // Dependency check: gemm needs convert_x/convert_w; scatter needs gemm +
    // deg pipeline; epilogue last. All hold.
    convert_x_kernel<<<2048, 256>>>(x);                                   // 0
    convert_w_kernel<<<(NGEMM * 65536 + 255) / 256, 256>>>(weight, wself);// 1
    zero_deg_kernel<<<(RREL * NNODES + 255) / 256, 256>>>();              // 2
    wmma_gemm_kernel<<<dim3(391, 2, NGEMM), 128, SMEM_BYTES>>>();         // 3
    deg_kernel<<<(RREL * EDGES + 255) / 256, 256>>>(dst);                 // 4
    invdeg_kernel<<<(RREL * NNODES + 255) / 256, 256>>>();                // 5

    int sblocks = (RREL * EDGES * 32 + 255) / 256;   // 40000
    scatter_all_kernel<<<sblocks, 256>>>(src, dst);                       // 6

    epilogue_kernel<<<(NNODES * 64 + 255) / 256, 256>>>(bias, out);       // 7
}

// round 10
// speedup vs baseline: 4.1151x; 1.6946x over previous
#include <cuda_runtime.h>
#include <cuda_bf16.h>
#include <cuda_fp16.h>
#include <mma.h>
#include <cstdint>

using namespace nvcuda;

#define NNODES 50000
#define NPAD   50048      // padded rows so store_matrix_sync never goes OOB
#define RREL   4
#define EDGES  80000
#define NGEMM  5          // slot 0 = self-loop, 1..4 = relations

// ---------------------------------------------------------------------------
// Static device scratch. Device code references symbols directly (R2 lesson:
// host-shadow addresses silently read host memory via ATS on GB300).
// ---------------------------------------------------------------------------
__device__ float  g_Hp[(size_t)NGEMM * NPAD * 256];    // 256.2 MB
__device__ int    g_deg[RREL * NNODES];
__device__ float  g_invdeg[RREL * NNODES];
__device__ __half g_x_h[(size_t)NNODES * 256];         // fp16 copy of x
__device__ __half g_w_h[NGEMM * 256 * 256];            // [g][n][k] (W transposed)

// ---------------------------------------------------------------------------
// degree pipeline
// ---------------------------------------------------------------------------
__global__ void zero_deg_kernel() {
    int i = blockIdx.x * blockDim.x + threadIdx.x;
    if (i < RREL * NNODES) g_deg[i] = 0;
}
__global__ void deg_kernel(const int* __restrict__ dst) {
    int i = blockIdx.x * blockDim.x + threadIdx.x;
    if (i < RREL * EDGES) {
        int r = i / EDGES;
        atomicAdd(&g_deg[r * NNODES + dst[i]], 1);
    }
}
__global__ void invdeg_kernel() {
    int i = blockIdx.x * blockDim.x + threadIdx.x;
    if (i < RREL * NNODES)
        g_invdeg[i] = 1.0f / fmaxf((float)g_deg[i], 1.0f);
}

// ---------------------------------------------------------------------------
// Prep: cast x to fp16 (shared A operand of all 5 GEMMs)
// ---------------------------------------------------------------------------
__global__ void convert_x_kernel(const float* __restrict__ x) {
    size_t total = (size_t)NNODES * 64;   // float4 count
    for (size_t i = (size_t)blockIdx.x * blockDim.x + threadIdx.x; i < total;
         i += (size_t)gridDim.x * blockDim.x) {
        float4 v = reinterpret_cast<const float4*>(x)[i];
        __half2 h01 = __float22half2_rn(make_float2(v.x, v.y));
        __half2 h23 = __float22half2_rn(make_float2(v.z, v.w));
        reinterpret_cast<__half2*>(g_x_h)[2 * i]     = h01;
        reinterpret_cast<__half2*>(g_x_h)[2 * i + 1] = h23;
    }
}

// Prep: transpose+cast weights into B layout W_t[g][n][k] = W_g[k][n]
__global__ void convert_w_kernel(const float* __restrict__ weight,
                                 const float* __restrict__ wself) {
    int i = blockIdx.x * blockDim.x + threadIdx.x;
    if (i >= NGEMM * 65536) return;
    int g = i >> 16;
    int n = (i >> 8) & 255;
    int k = i & 255;
    const float* src = (g == 0) ? wself : weight + (size_t)(g - 1) * 65536;
    g_w_h[i] = __float2half_rn(src[k * 256 + n]);
}

// ---------------------------------------------------------------------------
// fp16 wmma GEMM, cp.async double-buffered, warp tile 64x64.
// g_Hp[g][:, n0:n0+128] = x_h @ W_h^T   (single term, fp32 accumulate)
// grid (391, 2, 5), 128 threads (4 warps, 2x2). Block tile 128x128, KC=32.
// Dynamic smem: 2 stages x 2 matrices x [128][LDS] half = 40960 B.
// ---------------------------------------------------------------------------
#define KC   32
#define LDS  40                   // row stride (halves); 80 B
#define TILE_ELEMS (128 * LDS)    // 5120

__device__ __forceinline__ uint32_t smem_u32(const void* p) {
    uint32_t a;
    asm("{ .reg .u64 t; cvta.to.shared.u64 t, %1; cvt.u32.u64 %0, t; }" : "=r"(a) : "l"(p));
    return a;
}
__device__ __forceinline__ void cpa16(uint32_t dst, const void* src) {
    asm volatile("cp.async.cg.shared.global [%0], [%1], 16;" :: "r"(dst), "l"(src));
}
__device__ __forceinline__ void cpa16_zfill(uint32_t dst, const void* src) {
    asm volatile("cp.async.cg.shared.global [%0], [%1], 16, 0;" :: "r"(dst), "l"(src));
}

__global__ void __launch_bounds__(128)
wmma_gemm_kernel() {
    extern __shared__ __half smem[];

    const int tid = threadIdx.x;
    const int wid = tid >> 5;
    const int wm  = wid & 1;          // warp rows wm*64..+63
    const int wn  = wid >> 1;         // warp cols wn*64..+63
    const int m0  = blockIdx.x * 128;
    const int n0  = blockIdx.y * 128;
    const int g   = blockIdx.z;

    const __half* wh = g_w_h + (size_t)g * 65536;

    // per-thread load coords: 512 uint4 per matrix tile, 4 per thread
    const int lrow0 = tid >> 2;                 // 0..31
    const int lc4   = tid & 3;                  // uint4 slot in 32-wide k row

    auto issue_tile = [&](int t) {
        const int k0 = t * KC;
        const int stage = t & 1;
        __half* As = smem + (stage * 2 + 0) * TILE_ELEMS;
        __half* Bs = smem + (stage * 2 + 1) * TILE_ELEMS;
        #pragma unroll
        for (int p = 0; p < 4; p++) {
            int row = lrow0 + p * 32;
            int kof = k0 + lc4 * 8;
            uint32_t soff = (uint32_t)(row * LDS + lc4 * 8) * 2;  // bytes
            int gm = m0 + row;
            if (gm < NNODES) {
                cpa16(smem_u32(As) + soff, g_x_h + (size_t)gm * 256 + kof);
            } else {
                cpa16_zfill(smem_u32(As) + soff, g_x_h);
            }
            int n = n0 + row;
            cpa16(smem_u32(Bs) + soff, wh + (size_t)n * 256 + kof);
        }
        asm volatile("cp.async.commit_group;" ::: "memory");
    };

    wmma::fragment<wmma::accumulator, 16, 16, 16, float> c[4][4];
    #pragma unroll
    for (int mi = 0; mi < 4; mi++)
        #pragma unroll
        for (int ni = 0; ni < 4; ni++)
            wmma::fill_fragment(c[mi][ni], 0.0f);

    issue_tile(0);

    for (int t = 0; t < 8; t++) {
        if (t + 1 < 8) {
            issue_tile(t + 1);
            asm volatile("cp.async.wait_group 1;" ::: "memory");
        } else {
            asm volatile("cp.async.wait_group 0;" ::: "memory");
        }
        __syncthreads();   // stage t data visible to all warps

        const int stage = t & 1;
        const __half* As = smem + (stage * 2 + 0) * TILE_ELEMS;
        const __half* Bs = smem + (stage * 2 + 1) * TILE_ELEMS;

        #pragma unroll
        for (int ks = 0; ks < 2; ks++) {
            const int kk = ks * 16;
            wmma::fragment<wmma::matrix_a, 16, 16, 16, __half, wmma::row_major> a[4];
            wmma::fragment<wmma::matrix_b, 16, 16, 16, __half, wmma::col_major> b[4];
            #pragma unroll
            for (int mi = 0; mi < 4; mi++)
                wmma::load_matrix_sync(a[mi], As + (wm * 64 + mi * 16) * LDS + kk, LDS);
            #pragma unroll
            for (int ni = 0; ni < 4; ni++)
                wmma::load_matrix_sync(b[ni], Bs + (wn * 64 + ni * 16) * LDS + kk, LDS);
            #pragma unroll
            for (int mi = 0; mi < 4; mi++)
                #pragma unroll
                for (int ni = 0; ni < 4; ni++)
                    wmma::mma_sync(c[mi][ni], a[mi], b[ni], c[mi][ni]);
        }
        __syncthreads();   // all warps done with stage t before it is reloaded
    }

    // store into padded H (rows < 50048 always in-bounds)
    float* Cg = g_Hp + (size_t)g * NPAD * 256;
    #pragma unroll
    for (int mi = 0; mi < 4; mi++)
        #pragma unroll
        for (int ni = 0; ni < 4; ni++) {
            int row = m0 + wm * 64 + mi * 16;
            int col = n0 + wn * 64 + ni * 16;
            wmma::store_matrix_sync(Cg + (size_t)row * 256 + col, c[mi][ni],
                                    256, wmma::mem_row_major);
        }
}

// ---------------------------------------------------------------------------
// Scatter ALL relations in one launch: Hp[0][d] += invdeg[r][d] * Hp[r+1][s]
// (one warp per edge; Hp[0] already holds the self-loop term)
// ---------------------------------------------------------------------------
__global__ void scatter_all_kernel(const int* __restrict__ src,
                                   const int* __restrict__ dst) {
    int gw   = (blockIdx.x * blockDim.x + threadIdx.x) >> 5;
    int lane = threadIdx.x & 31;
    if (gw >= RREL * EDGES) return;
    int r = gw / EDGES;
    int s = src[gw];
    int d = dst[gw];
    float w = g_invdeg[r * NNODES + d];

    const float4* h = reinterpret_cast<const float4*>(
        g_Hp + ((size_t)(r + 1) * NPAD + s) * 256);
    float* ob = g_Hp + (size_t)d * 256;     // accumulate into Hp[0]
    #pragma unroll
    for (int i = 0; i < 2; i++) {
        float4 v = __ldg(&h[lane + i * 32]);
        v.x *= w; v.y *= w; v.z *= w; v.w *= w;
        float* a = ob + (size_t)(lane + i * 32) * 4;
        asm volatile("red.global.add.v4.f32 [%0], {%1,%2,%3,%4};"
                     :: "l"(a), "f"(v.x), "f"(v.y), "f"(v.z), "f"(v.w) : "memory");
    }
}

// ---------------------------------------------------------------------------
// Epilogue: out = relu(Hp[0] + bias)
// ---------------------------------------------------------------------------
__global__ void epilogue_kernel(const float* __restrict__ bias,
                                float* __restrict__ out) {
    size_t i = (size_t)blockIdx.x * blockDim.x + threadIdx.x;
    size_t total4 = (size_t)NNODES * 64;
    if (i < total4) {
        float4 v = reinterpret_cast<const float4*>(g_Hp)[i];
        int c = (int)(i & 63) * 4;
        v.x = fmaxf(v.x + bias[c + 0], 0.f);
        v.y = fmaxf(v.y + bias[c + 1], 0.f);
        v.z = fmaxf(v.z + bias[c + 2], 0.f);
        v.w = fmaxf(v.w + bias[c + 3], 0.f);
        reinterpret_cast<float4*>(out)[i] = v;
    }
}

// ---------------------------------------------------------------------------
extern "C" void kernel_launch(void* const* d_in, const int* in_sizes, int n_in,
                              void* d_out, int out_size) {
    const float* x      = (const float*)d_in[0];
    const int*   src    = (const int*)  d_in[1];
    const int*   dst    = (const int*)  d_in[2];
    const float* weight = (const float*)d_in[3];
    const float* wself  = (const float*)d_in[4];
    const float* bias   = (const float*)d_in[5];
    float* out = (float*)d_out;

    // Launch order keeps wmma_gemm at captured-profile index 3.
    // Dependencies: gemm needs convert_x/convert_w; scatter needs gemm +
    // deg pipeline; epilogue last. All hold.
    convert_x_kernel<<<2048, 256>>>(x);                                   // 0
    convert_w_kernel<<<(NGEMM * 65536 + 255) / 256, 256>>>(weight, wself);// 1
    zero_deg_kernel<<<(RREL * NNODES + 255) / 256, 256>>>();              // 2
    wmma_gemm_kernel<<<dim3(391, 2, NGEMM), 128, 40960>>>();              // 3
    deg_kernel<<<(RREL * EDGES + 255) / 256, 256>>>(dst);                 // 4
    invdeg_kernel<<<(RREL * NNODES + 255) / 256, 256>>>();                // 5

    int sblocks = (RREL * EDGES * 32 + 255) / 256;   // 40000
    scatter_all_kernel<<<sblocks, 256>>>(src, dst);                       // 6

    epilogue_kernel<<<(NNODES * 64 + 255) / 256, 256>>>(bias, out);       // 7
}